// round 2
// baseline (speedup 1.0000x reference)
#include <cuda_runtime.h>
#include <math.h>

#define NPIX 16384
#define BN   65536   // 4 * 16384

// ------------ scratch ------------------------------------------------------
__device__ float g_k[64*BN];
__device__ float g_v[64*BN];
__device__ float g_q[64*BN];
__device__ float g_xm[64*BN];
__device__ float g_Gpart[4*64*1024];
__device__ float g_sqp[4*64*64];
__device__ float g_skp[4*64*64];
__device__ float g_A[4096];
__device__ float g_weffT[4*4096];
__device__ float g_wcatT[4096];
__device__ float g_inwT[4096];
__device__ float g_wkT[4096];
__device__ float g_wvT[4096];
__device__ float g_wqT[4096];
__device__ float g_w1T[8192];
__device__ float g_w2T[16384];
__device__ float g_bcat[64];

__device__ __forceinline__ float dot64(const float* w, const float* xr) {
    const float4* w4 = (const float4*)w;
    float a0=0.f,a1=0.f,a2=0.f,a3=0.f;
    #pragma unroll
    for (int i=0;i<16;i++){
        float4 wv=w4[i];
        a0=fmaf(xr[4*i+0],wv.x,a0); a1=fmaf(xr[4*i+1],wv.y,a1);
        a2=fmaf(xr[4*i+2],wv.z,a2); a3=fmaf(xr[4*i+3],wv.w,a3);
    }
    return (a0+a1)+(a2+a3);
}
__device__ __forceinline__ float dot128(const float* w, const float* xr) {
    const float4* w4 = (const float4*)w;
    float a0=0.f,a1=0.f,a2=0.f,a3=0.f;
    #pragma unroll
    for (int i=0;i<32;i++){
        float4 wv=w4[i];
        a0=fmaf(xr[4*i+0],wv.x,a0); a1=fmaf(xr[4*i+1],wv.y,a1);
        a2=fmaf(xr[4*i+2],wv.z,a2); a3=fmaf(xr[4*i+3],wv.w,a3);
    }
    return (a0+a1)+(a2+a3);
}

// ------------ kprep: fold + transpose weights ------------------------------
__global__ void kprep(const float* wa, const float* ba, const float* wb, const float* bb,
                      const float* inw, const float* wk, const float* wv, const float* wq,
                      const float* w1, const float* w2)
{
    int t = blockIdx.x*256 + threadIdx.x;     // 0..16383
    if (t < 4096) {
        int j = t>>6, c = t&63;
        float w;
        if (j < 4) w = wa[c*4 + j];
        else { int u=j-4; int kk=u/3; int d=u-kk*3; w = wb[kk*192 + c*3 + d]; }
        g_wcatT[t] = w;
        g_inwT[t]  = inw[c*64 + j];
        g_wkT[t]   = wk[c*64 + j];
        g_wvT[t]   = wv[c*64 + j];
        g_wqT[t]   = wq[c*64 + j];
    }
    if (t < 8192)  { int o=t>>6, c=t&63;  g_w1T[t] = w1[c*128 + o]; }
    if (t < 16384) { int o=t>>7, i=t&127; g_w2T[t] = w2[i*128 + o]; }
    if (t < 64) g_bcat[t] = (t < 4) ? ba[t] : bb[t-4];
}

// ------------ k1: feat path -> y -> k, v ------------------------------------
__global__ void __launch_bounds__(256,2)
k1(const float* __restrict__ x, const float* __restrict__ sem,
   const float* __restrict__ inb, const float* __restrict__ bk, const float* __restrict__ bv)
{
    extern __shared__ float sm[];
    float* s_w    = sm;           // 4096
    float* s_sem  = sm + 4096;    // 5376
    float* s_stg  = sm + 9472;    // 16384
    float* s_bias = sm + 25856;   // 256
    int t = threadIdx.x;
    int gp = blockIdx.x*256 + t;
    int b = gp >> 14, p = gp & (NPIX-1);

    for (int i=t;i<4096;i+=256) s_w[i]=g_wcatT[i];
    if (t<64){ s_bias[t]=g_bcat[t]; s_bias[64+t]=inb[t]; s_bias[128+t]=bk[t]; s_bias[192+t]=bv[t]; }
    int sbase = b*21*NPIX + p;
    #pragma unroll
    for (int kk=0;kk<21;kk++){ float sv=sem[sbase+kk*NPIX]; s_sem[kk*256+t]=sv>0.f?sv:0.f; }
    float xr[64];
    int xbase = b*64*NPIX + p;
    #pragma unroll
    for (int c=0;c<64;c++) xr[c]=x[xbase+c*NPIX];
    __syncthreads();

    for (int j=0;j<64;j++){
        float d = dot64(s_w+j*64, xr);
        int cls = (j<4) ? 0 : ((j-4)/3 + 1);
        s_stg[j*256+t] = s_sem[cls*256+t]*d + s_bias[j];
    }
    float af[64];
    #pragma unroll
    for (int j=0;j<64;j++) af[j]=s_stg[j*256+t];
    __syncthreads();
    for (int i=t;i<4096;i+=256) s_w[i]=g_inwT[i];
    __syncthreads();
    for (int o=0;o<64;o++) s_stg[o*256+t] = dot64(s_w+o*64, af) + s_bias[64+o];
    float yr[64];
    #pragma unroll
    for (int o=0;o<64;o++) yr[o]=s_stg[o*256+t];
    __syncthreads();
    for (int i=t;i<4096;i+=256) s_w[i]=g_wkT[i];
    __syncthreads();
    for (int o=0;o<64;o++) g_k[o*BN+gp] = dot64(s_w+o*64, yr) + s_bias[128+o];
    __syncthreads();
    for (int i=t;i<4096;i+=256) s_w[i]=g_wvT[i];
    __syncthreads();
    for (int o=0;o<64;o++) g_v[o*BN+gp] = dot64(s_w+o*64, yr) + s_bias[192+o];
}

// ------------ k2: LN-MLP -> xm, q -------------------------------------------
__global__ void __launch_bounds__(256,1)
k2(const float* __restrict__ x,
   const float* __restrict__ b1, const float* __restrict__ gm1, const float* __restrict__ be1,
   const float* __restrict__ b2, const float* __restrict__ gm2, const float* __restrict__ be2,
   const float* __restrict__ w3, const float* __restrict__ b3, const float* __restrict__ bq)
{
    extern __shared__ float sm[];
    float* wbuf = sm;            // 16384
    float* hbuf = sm + 16384;    // 32768
    float* s_p  = sm + 49152;    // 896
    int t = threadIdx.x;
    int gp = blockIdx.x*256 + t;
    int b = gp >> 14, p = gp & (NPIX-1);
    for (int i=t;i<128;i+=256){
        s_p[i]=b1[i]; s_p[128+i]=gm1[i]; s_p[256+i]=be1[i];
        s_p[384+i]=b2[i]; s_p[512+i]=gm2[i]; s_p[640+i]=be2[i];
    }
    if (t<64){ s_p[768+t]=b3[t]; s_p[832+t]=bq[t]; }
    for (int i=t;i<8192;i+=256) wbuf[i]=g_w1T[i];
    float xr[64];
    int xbase = b*64*NPIX + p;
    #pragma unroll
    for (int c=0;c<64;c++) xr[c]=x[xbase+c*NPIX];
    __syncthreads();

    float s=0.f, s2=0.f;
    for (int o=0;o<128;o++){
        float u = dot64(wbuf+o*64, xr) + s_p[o];
        hbuf[o*256+t]=u; s+=u; s2=fmaf(u,u,s2);
    }
    float m=s*(1.f/128.f), var=s2*(1.f/128.f)-m*m, rinv=rsqrtf(var+1e-5f);
    float h1[128];
    #pragma unroll
    for (int i=0;i<128;i++){
        float v=(hbuf[i*256+t]-m)*rinv*s_p[128+i]+s_p[256+i];
        h1[i]=v>0.f?v:0.01f*v;
    }
    __syncthreads();
    for (int i=t;i<16384;i+=256) wbuf[i]=g_w2T[i];
    __syncthreads();
    s=0.f; s2=0.f;
    for (int o=0;o<128;o++){
        float u = dot128(wbuf+o*128, h1) + s_p[384+o];
        hbuf[o*256+t]=u; s+=u; s2=fmaf(u,u,s2);
    }
    m=s*(1.f/128.f); var=s2*(1.f/128.f)-m*m; rinv=rsqrtf(var+1e-5f);
    __syncthreads();
    for (int i=t;i<8192;i+=256) wbuf[i]=w3[i];
    for (int i=t;i<4096;i+=256) wbuf[8192+i]=g_wqT[i];
    __syncthreads();
    float xm[64];
    #pragma unroll
    for (int c=0;c<64;c++) xm[c]=s_p[768+c];
    for (int i=0;i<128;i++){
        float u=hbuf[i*256+t];
        float v=(u-m)*rinv*s_p[512+i]+s_p[640+i];
        v=v>0.f?v:0.01f*v;
        const float4* w4=(const float4*)(wbuf+i*64);
        #pragma unroll
        for (int c4=0;c4<16;c4++){
            float4 wv=w4[c4];
            xm[4*c4+0]=fmaf(v,wv.x,xm[4*c4+0]);
            xm[4*c4+1]=fmaf(v,wv.y,xm[4*c4+1]);
            xm[4*c4+2]=fmaf(v,wv.z,xm[4*c4+2]);
            xm[4*c4+3]=fmaf(v,wv.w,xm[4*c4+3]);
        }
    }
    #pragma unroll
    for (int c=0;c<64;c++) g_xm[c*BN+gp]=xm[c];
    for (int j=0;j<64;j++) g_q[j*BN+gp] = dot64(wbuf+8192+j*64, xm) + s_p[832+j];
}

// ------------ k3: Gram + norm partials per 256-pixel chunk ------------------
#define TPAD 257
__global__ void __launch_bounds__(256,1) k3()
{
    extern __shared__ float sm[];
    float* qs  = sm;
    float* ks  = sm + 64*TPAD;
    float* red = sm + 128*TPAD;   // 4096
    int t = threadIdx.x;
    int chunk = blockIdx.x, b = blockIdx.y;
    int pbase = b*NPIX + chunk*256;
    for (int ch=0; ch<64; ch++){
        qs[ch*TPAD+t]=g_q[ch*BN+pbase+t];
        ks[ch*TPAD+t]=g_k[ch*BN+pbase+t];
    }
    __syncthreads();
    int sub=t>>6, combo=t&63;
    int h=combo>>4, d4=(combo>>2)&3, e4=combo&3;
    const float* qsb=qs+(h*16+d4*4)*TPAD;
    const float* ksb=ks+(h*16+e4*4)*TPAD;
    float acc[4][4];
    #pragma unroll
    for (int i=0;i<4;i++)
        #pragma unroll
        for (int j=0;j<4;j++) acc[i][j]=0.f;
    for (int pp=sub*64; pp<sub*64+64; pp++){
        float q0=qsb[pp],q1=qsb[TPAD+pp],q2=qsb[2*TPAD+pp],q3=qsb[3*TPAD+pp];
        float k0=ksb[pp],k1v=ksb[TPAD+pp],k2v=ksb[2*TPAD+pp],k3v=ksb[3*TPAD+pp];
        acc[0][0]=fmaf(q0,k0,acc[0][0]); acc[0][1]=fmaf(q0,k1v,acc[0][1]); acc[0][2]=fmaf(q0,k2v,acc[0][2]); acc[0][3]=fmaf(q0,k3v,acc[0][3]);
        acc[1][0]=fmaf(q1,k0,acc[1][0]); acc[1][1]=fmaf(q1,k1v,acc[1][1]); acc[1][2]=fmaf(q1,k2v,acc[1][2]); acc[1][3]=fmaf(q1,k3v,acc[1][3]);
        acc[2][0]=fmaf(q2,k0,acc[2][0]); acc[2][1]=fmaf(q2,k1v,acc[2][1]); acc[2][2]=fmaf(q2,k2v,acc[2][2]); acc[2][3]=fmaf(q2,k3v,acc[2][3]);
        acc[3][0]=fmaf(q3,k0,acc[3][0]); acc[3][1]=fmaf(q3,k1v,acc[3][1]); acc[3][2]=fmaf(q3,k2v,acc[3][2]); acc[3][3]=fmaf(q3,k3v,acc[3][3]);
    }
    #pragma unroll
    for (int i=0;i<4;i++)
        #pragma unroll
        for (int j=0;j<4;j++)
            red[sub*1024 + (h*16+d4*4+i)*16 + (e4*4+j)] = acc[i][j];
    if (t < 64){
        const float* qr=qs+t*TPAD;
        float a0=0,a1=0,a2=0,a3=0;
        for (int pp=0;pp<256;pp+=4){
            a0=fmaf(qr[pp+0],qr[pp+0],a0); a1=fmaf(qr[pp+1],qr[pp+1],a1);
            a2=fmaf(qr[pp+2],qr[pp+2],a2); a3=fmaf(qr[pp+3],qr[pp+3],a3);
        }
        g_sqp[(b*64+chunk)*64+t]=(a0+a1)+(a2+a3);
    } else if (t < 128){
        int ch=t-64;
        const float* kr=ks+ch*TPAD;
        float a0=0,a1=0,a2=0,a3=0;
        for (int pp=0;pp<256;pp+=4){
            a0=fmaf(kr[pp+0],kr[pp+0],a0); a1=fmaf(kr[pp+1],kr[pp+1],a1);
            a2=fmaf(kr[pp+2],kr[pp+2],a2); a3=fmaf(kr[pp+3],kr[pp+3],a3);
        }
        g_skp[(b*64+chunk)*64+ch]=(a0+a1)+(a2+a3);
    }
    __syncthreads();
    float* gout = g_Gpart + (b*64+chunk)*1024;
    for (int idx=t; idx<1024; idx+=256)
        gout[idx] = (red[idx]+red[1024+idx]) + (red[2048+idx]+red[3072+idx]);
}

// ------------ k4: reduce + normalize + softmax -> A --------------------------
__global__ void k4(const float* __restrict__ rescale)
{
    __shared__ float sG[1024];
    __shared__ float snq[64], snk[64];
    int b=blockIdx.x, t=threadIdx.x;
    for (int idx=t; idx<1024; idx+=256){
        float a=0.f;
        for (int c=0;c<64;c++) a += g_Gpart[(b*64+c)*1024+idx];
        sG[idx]=a;
    }
    if (t<64){
        float aq=0.f, ak=0.f;
        for (int c=0;c<64;c++){ aq+=g_sqp[(b*64+c)*64+t]; ak+=g_skp[(b*64+c)*64+t]; }
        snq[t]=sqrtf(aq)+1e-8f; snk[t]=sqrtf(ak)+1e-8f;
    }
    __syncthreads();
    if (t<64){
        int h=t>>4;
        float r=rescale[h], nq=snq[t];
        float ev[16]; float mx=-1e30f;
        #pragma unroll
        for (int e=0;e<16;e++){ ev[e]=sG[t*16+e]/(nq*snk[h*16+e])*r; mx=fmaxf(mx,ev[e]); }
        float ss=0.f;
        #pragma unroll
        for (int e=0;e<16;e++){ ev[e]=expf(ev[e]-mx); ss+=ev[e]; }
        float inv=1.f/ss;
        #pragma unroll
        for (int e=0;e<16;e++) g_A[b*1024 + t*16+e]=ev[e]*inv;
    }
}

// ------------ k4b: Weff[b] = blockdiag(A)^T folded into wo -------------------
__global__ void k4b(const float* __restrict__ wo)
{
    __shared__ float sA[1024];
    __shared__ float swo[4096];
    int b=blockIdx.x, t=threadIdx.x;
    for (int i=t;i<1024;i+=256) sA[i]=g_A[b*1024+i];
    for (int i=t;i<4096;i+=256) swo[i]=wo[i];
    __syncthreads();
    for (int idx=t; idx<4096; idx+=256){
        int cp=idx>>6, e=idx&63, h=e>>4, e15=e&15;
        float acc=0.f;
        #pragma unroll
        for (int d=0;d<16;d++)
            acc = fmaf(sA[h*256 + d*16 + e15], swo[(h*16+d)*64 + cp], acc);
        g_weffT[b*4096 + cp*64 + e] = acc;
    }
}

// ------------ k5: out = v @ WeffT + bo + xm ----------------------------------
__global__ void __launch_bounds__(256,2)
k5(const float* __restrict__ bo, float* __restrict__ out)
{
    __shared__ float sw[4096];
    __shared__ float sbo[64];
    int t=threadIdx.x;
    int gp=blockIdx.x*256+t;
    int b=gp>>14, p=gp&(NPIX-1);
    for (int i=t;i<4096;i+=256) sw[i]=g_weffT[b*4096+i];
    if (t<64) sbo[t]=bo[t];
    float vr[64];
    #pragma unroll
    for (int e=0;e<64;e++) vr[e]=g_v[e*BN+gp];
    __syncthreads();
    for (int cp=0;cp<64;cp++){
        float d = dot64(sw+cp*64, vr) + sbo[cp] + g_xm[cp*BN+gp];
        out[(size_t)(b*64+cp)*NPIX + p] = d;
    }
}

// ------------ launch ----------------------------------------------------------
extern "C" void kernel_launch(void* const* d_in, const int* in_sizes, int n_in,
                              void* d_out, int out_size)
{
    const float* x   =(const float*)d_in[0];
    const float* sem =(const float*)d_in[1];
    const float* wa  =(const float*)d_in[2];
    const float* ba  =(const float*)d_in[3];
    const float* wb  =(const float*)d_in[4];
    const float* bb  =(const float*)d_in[5];
    const float* inw =(const float*)d_in[6];
    const float* inb =(const float*)d_in[7];
    const float* w1  =(const float*)d_in[8];
    const float* b1  =(const float*)d_in[9];
    const float* gm1 =(const float*)d_in[10];
    const float* be1 =(const float*)d_in[11];
    const float* w2  =(const float*)d_in[12];
    const float* b2  =(const float*)d_in[13];
    const float* gm2 =(const float*)d_in[14];
    const float* be2 =(const float*)d_in[15];
    const float* w3  =(const float*)d_in[16];
    const float* b3  =(const float*)d_in[17];
    const float* wq  =(const float*)d_in[18];
    const float* bq  =(const float*)d_in[19];
    const float* wk  =(const float*)d_in[20];
    const float* bk  =(const float*)d_in[21];
    const float* wv  =(const float*)d_in[22];
    const float* bv  =(const float*)d_in[23];
    const float* wo  =(const float*)d_in[24];
    const float* bo  =(const float*)d_in[25];
    const float* rescale=(const float*)d_in[26];
    float* out=(float*)d_out;

    cudaFuncSetAttribute(k1, cudaFuncAttributeMaxDynamicSharedMemorySize, 26112*4);
    cudaFuncSetAttribute(k2, cudaFuncAttributeMaxDynamicSharedMemorySize, 50048*4);
    cudaFuncSetAttribute(k3, cudaFuncAttributeMaxDynamicSharedMemorySize, 36992*4);

    kprep<<<64,256>>>(wa,ba,wb,bb,inw,wk,wv,wq,w1,w2);
    k1<<<256,256,26112*4>>>(x,sem,inb,bk,bv);
    k2<<<256,256,50048*4>>>(x,b1,gm1,be1,b2,gm2,be2,w3,b3,bq);
    k3<<<dim3(64,4),256,36992*4>>>();
    k4<<<4,256>>>(rescale);
    k4b<<<4,256>>>(wo);
    k5<<<256,256>>>(bo,out);
}

// round 3
// speedup vs baseline: 1.0872x; 1.0872x over previous
#include <cuda_runtime.h>
#include <math.h>

#define NPIX 16384
#define BN   65536   // 4 * 16384

typedef unsigned long long u64;

// ------------ scratch ------------------------------------------------------
__device__ float g_k[64*BN];
__device__ float g_v[64*BN];
__device__ float g_q[64*BN];
__device__ float g_xm[64*BN];
__device__ float g_Gpart[4*64*1024];
__device__ float g_sqp[4*64*64];
__device__ float g_skp[4*64*64];
__device__ float g_A[4096];
__device__ float g_weffT[4*4096];
__device__ float g_wcatT[4096];
__device__ float g_inwT[4096];
__device__ float g_wkT[4096];
__device__ float g_wvT[4096];
__device__ float g_wqT[4096];
__device__ float g_w1T[8192];
__device__ float g_w2T[16384];
__device__ float g_bcat[64];

// ------------ f32x2 helpers --------------------------------------------------
__device__ __forceinline__ u64 pack2(float lo, float hi){
    u64 r; asm("mov.b64 %0, {%1,%2};" : "=l"(r) : "f"(lo), "f"(hi)); return r;
}
__device__ __forceinline__ void unpack2(u64 a, float& lo, float& hi){
    asm("mov.b64 {%0,%1}, %2;" : "=f"(lo), "=f"(hi) : "l"(a));
}
__device__ __forceinline__ u64 fma2_(u64 a, u64 b, u64 c){
    u64 d; asm("fma.rn.f32x2 %0, %1, %2, %3;" : "=l"(d) : "l"(a), "l"(b), "l"(c)); return d;
}
__device__ __forceinline__ u64 add2_(u64 a, u64 b){
    u64 d; asm("add.rn.f32x2 %0, %1, %2;" : "=l"(d) : "l"(a), "l"(b)); return d;
}
__device__ __forceinline__ float hadd2(u64 a){
    float lo, hi; unpack2(a, lo, hi); return lo + hi;
}

// packed dot: x packed (c,c+1), w contiguous 64 floats (16B aligned)
__device__ __forceinline__ float dot64p(const float* w, const u64* xp){
    const ulonglong2* w2 = (const ulonglong2*)w;
    u64 a0=0ull,a1=0ull,a2=0ull,a3=0ull;
    #pragma unroll
    for (int i=0;i<8;i++){
        ulonglong2 wa=w2[2*i], wb=w2[2*i+1];
        a0=fma2_(xp[4*i+0], wa.x, a0);
        a1=fma2_(xp[4*i+1], wa.y, a1);
        a2=fma2_(xp[4*i+2], wb.x, a2);
        a3=fma2_(xp[4*i+3], wb.y, a3);
    }
    return hadd2(add2_(add2_(a0,a1),add2_(a2,a3)));
}
__device__ __forceinline__ float dot128p(const float* w, const u64* xp){
    const ulonglong2* w2 = (const ulonglong2*)w;
    u64 a0=0ull,a1=0ull,a2=0ull,a3=0ull;
    #pragma unroll
    for (int i=0;i<16;i++){
        ulonglong2 wa=w2[2*i], wb=w2[2*i+1];
        a0=fma2_(xp[4*i+0], wa.x, a0);
        a1=fma2_(xp[4*i+1], wa.y, a1);
        a2=fma2_(xp[4*i+2], wb.x, a2);
        a3=fma2_(xp[4*i+3], wb.y, a3);
    }
    return hadd2(add2_(add2_(a0,a1),add2_(a2,a3)));
}

// ------------ kprep: fold + transpose weights ------------------------------
__global__ void kprep(const float* wa, const float* ba, const float* wb, const float* bb,
                      const float* inw, const float* wk, const float* wv, const float* wq,
                      const float* w1, const float* w2)
{
    int t = blockIdx.x*256 + threadIdx.x;     // 0..16383
    if (t < 4096) {
        int j = t>>6, c = t&63;
        float w;
        if (j < 4) w = wa[c*4 + j];
        else { int u=j-4; int kk=u/3; int d=u-kk*3; w = wb[kk*192 + c*3 + d]; }
        g_wcatT[t] = w;
        g_inwT[t]  = inw[c*64 + j];
        g_wkT[t]   = wk[c*64 + j];
        g_wvT[t]   = wv[c*64 + j];
        g_wqT[t]   = wq[c*64 + j];
    }
    if (t < 8192)  { int o=t>>6, c=t&63;  g_w1T[t] = w1[c*128 + o]; }
    if (t < 16384) { int o=t>>7, i=t&127; g_w2T[t] = w2[i*128 + o]; }
    if (t < 64) g_bcat[t] = (t < 4) ? ba[t] : bb[t-4];
}

// ------------ k1: feat path -> y -> k, v ------------------------------------
// dyn smem: s_w 16384 | s_sem 5376 | s_bias 256  (floats) = 88064 B
__global__ void __launch_bounds__(256,1)
k1(const float* __restrict__ x, const float* __restrict__ sem,
   const float* __restrict__ inb, const float* __restrict__ bk, const float* __restrict__ bv)
{
    extern __shared__ float smx[];
    float* s_w    = smx;            // 4 x 4096
    float* s_sem  = smx + 16384;    // 5376
    float* s_bias = smx + 21760;    // 256
    int t = threadIdx.x;
    int gp = blockIdx.x*256 + t;
    int b = gp >> 14, p = gp & (NPIX-1);

    for (int i=t;i<4096;i+=256){
        s_w[i]       = g_wcatT[i];
        s_w[4096+i]  = g_inwT[i];
        s_w[8192+i]  = g_wkT[i];
        s_w[12288+i] = g_wvT[i];
    }
    if (t<64){ s_bias[t]=g_bcat[t]; s_bias[64+t]=inb[t]; s_bias[128+t]=bk[t]; s_bias[192+t]=bv[t]; }
    int sbase = b*21*NPIX + p;
    #pragma unroll
    for (int kk=0;kk<21;kk++){ float sv=sem[sbase+kk*NPIX]; s_sem[kk*256+t]=sv>0.f?sv:0.f; }

    u64 xp[32];
    int xbase = b*64*NPIX + p;
    #pragma unroll
    for (int c=0;c<64;c+=2) xp[c>>1]=pack2(x[xbase+c*NPIX], x[xbase+(c+1)*NPIX]);
    __syncthreads();

    // all_feat
    u64 ap[32];
    #pragma unroll 2
    for (int j=0;j<64;j+=2){
        float d0 = dot64p(s_w + j*64, xp);
        float d1 = dot64p(s_w + (j+1)*64, xp);
        int cls0 = (j   < 4) ? 0 : ((j-4)/3 + 1);
        int cls1 = (j+1 < 4) ? 0 : ((j-3)/3 + 1);
        float f0 = s_sem[cls0*256+t]*d0 + s_bias[j];
        float f1 = s_sem[cls1*256+t]*d1 + s_bias[j+1];
        ap[j>>1] = pack2(f0, f1);
    }
    // y = all_feat @ in_w + in_b
    u64 yp[32];
    #pragma unroll 2
    for (int o=0;o<64;o+=2){
        float d0 = dot64p(s_w + 4096 + o*64, ap) + s_bias[64+o];
        float d1 = dot64p(s_w + 4096 + (o+1)*64, ap) + s_bias[65+o];
        yp[o>>1] = pack2(d0, d1);
    }
    // k, v
    #pragma unroll 2
    for (int o=0;o<64;o++) g_k[o*BN+gp] = dot64p(s_w + 8192 + o*64, yp) + s_bias[128+o];
    #pragma unroll 2
    for (int o=0;o<64;o++) g_v[o*BN+gp] = dot64p(s_w + 12288 + o*64, yp) + s_bias[192+o];
}

// ------------ k2: LN-MLP -> xm, q -------------------------------------------
// dyn smem: wbuf 16384 f | hbuf 16384 u64 (=32768 f) | s_p 896 f  -> 200192 B
__global__ void __launch_bounds__(256,1)
k2(const float* __restrict__ x,
   const float* __restrict__ b1, const float* __restrict__ gm1, const float* __restrict__ be1,
   const float* __restrict__ b2, const float* __restrict__ gm2, const float* __restrict__ be2,
   const float* __restrict__ w3, const float* __restrict__ b3, const float* __restrict__ bq)
{
    extern __shared__ float smx[];
    float* wbuf = smx;                    // 16384
    u64*   hbuf = (u64*)(smx + 16384);    // 16384 u64
    float* s_p  = smx + 49152;            // 896
    int t = threadIdx.x;
    int gp = blockIdx.x*256 + t;
    int b = gp >> 14, p = gp & (NPIX-1);
    for (int i=t;i<128;i+=256){
        s_p[i]=b1[i]; s_p[128+i]=gm1[i]; s_p[256+i]=be1[i];
        s_p[384+i]=b2[i]; s_p[512+i]=gm2[i]; s_p[640+i]=be2[i];
    }
    if (t<64){ s_p[768+t]=b3[t]; s_p[832+t]=bq[t]; }
    for (int i=t;i<8192;i+=256) wbuf[i]=g_w1T[i];

    u64 xp[32];
    int xbase = b*64*NPIX + p;
    #pragma unroll
    for (int c=0;c<64;c+=2) xp[c>>1]=pack2(x[xbase+c*NPIX], x[xbase+(c+1)*NPIX]);
    __syncthreads();

    // layer 1: u = x@w1 + b1
    u64 sp=0ull, s2p=0ull;
    #pragma unroll 2
    for (int o=0;o<128;o+=2){
        float u0 = dot64p(wbuf + o*64, xp) + s_p[o];
        float u1 = dot64p(wbuf + (o+1)*64, xp) + s_p[o+1];
        u64 up = pack2(u0,u1);
        hbuf[(o>>1)*256 + t] = up;
        sp = add2_(sp, up);
        s2p = fma2_(up, up, s2p);
    }
    float s = hadd2(sp), s2 = hadd2(s2p);
    float m = s*(1.f/128.f), var = s2*(1.f/128.f)-m*m, rinv = rsqrtf(var+1e-5f);

    u64 hp[64];
    #pragma unroll
    for (int i=0;i<64;i++){
        float u0,u1; unpack2(hbuf[i*256+t], u0, u1);
        float v0=(u0-m)*rinv*s_p[128+2*i]+s_p[256+2*i];
        float v1=(u1-m)*rinv*s_p[128+2*i+1]+s_p[256+2*i+1];
        v0 = v0>0.f?v0:0.01f*v0;
        v1 = v1>0.f?v1:0.01f*v1;
        hp[i]=pack2(v0,v1);
    }
    __syncthreads();
    for (int i=t;i<16384;i+=256) wbuf[i]=g_w2T[i];
    __syncthreads();

    // layer 2
    sp=0ull; s2p=0ull;
    #pragma unroll 2
    for (int o=0;o<128;o+=2){
        float u0 = dot128p(wbuf + o*128, hp) + s_p[384+o];
        float u1 = dot128p(wbuf + (o+1)*128, hp) + s_p[384+o+1];
        u64 up = pack2(u0,u1);
        hbuf[(o>>1)*256 + t] = up;
        sp = add2_(sp, up);
        s2p = fma2_(up, up, s2p);
    }
    s = hadd2(sp); s2 = hadd2(s2p);
    m = s*(1.f/128.f); var = s2*(1.f/128.f)-m*m; rinv = rsqrtf(var+1e-5f);

    __syncthreads();
    for (int i=t;i<8192;i+=256) wbuf[i]=w3[i];
    for (int i=t;i<4096;i+=256) wbuf[8192+i]=g_wqT[i];
    __syncthreads();

    // layer 3: xm = lrelu(LN(h2)) @ w3 + b3, accumulated packed over channels
    u64 xmp[32];
    #pragma unroll
    for (int c=0;c<64;c+=2) xmp[c>>1] = pack2(s_p[768+c], s_p[768+c+1]);
    #pragma unroll 2
    for (int i=0;i<128;i+=2){
        float u0,u1; unpack2(hbuf[(i>>1)*256+t], u0, u1);
        float v0=(u0-m)*rinv*s_p[512+i]+s_p[640+i];
        float v1=(u1-m)*rinv*s_p[512+i+1]+s_p[640+i+1];
        v0 = v0>0.f?v0:0.01f*v0;
        v1 = v1>0.f?v1:0.01f*v1;
        u64 vv0=pack2(v0,v0), vv1=pack2(v1,v1);
        const ulonglong2* w0=(const ulonglong2*)(wbuf + i*64);
        const ulonglong2* w1p=(const ulonglong2*)(wbuf + (i+1)*64);
        #pragma unroll
        for (int c2=0;c2<16;c2++){
            ulonglong2 wa=w0[c2], wb=w1p[c2];
            xmp[2*c2+0]=fma2_(vv0, wa.x, xmp[2*c2+0]);
            xmp[2*c2+1]=fma2_(vv0, wa.y, xmp[2*c2+1]);
            xmp[2*c2+0]=fma2_(vv1, wb.x, xmp[2*c2+0]);
            xmp[2*c2+1]=fma2_(vv1, wb.y, xmp[2*c2+1]);
        }
    }
    #pragma unroll
    for (int c=0;c<64;c+=2){
        float v0,v1; unpack2(xmp[c>>1], v0, v1);
        g_xm[c*BN+gp]=v0; g_xm[(c+1)*BN+gp]=v1;
    }
    // q = xm @ wq + bq
    #pragma unroll 2
    for (int j=0;j<64;j++)
        g_q[j*BN+gp] = dot64p(wbuf + 8192 + j*64, xmp) + s_p[832+j];
}

// ------------ k3: Gram + norm partials per 256-pixel chunk ------------------
#define TPAD 257
__global__ void __launch_bounds__(256,1) k3()
{
    extern __shared__ float smx[];
    float* qs  = smx;
    float* ks  = smx + 64*TPAD;
    float* red = smx + 128*TPAD;   // 4096
    int t = threadIdx.x;
    int chunk = blockIdx.x, b = blockIdx.y;
    int pbase = b*NPIX + chunk*256;
    for (int ch=0; ch<64; ch++){
        qs[ch*TPAD+t]=g_q[ch*BN+pbase+t];
        ks[ch*TPAD+t]=g_k[ch*BN+pbase+t];
    }
    __syncthreads();
    int sub=t>>6, combo=t&63;
    int h=combo>>4, d4=(combo>>2)&3, e4=combo&3;
    const float* qsb=qs+(h*16+d4*4)*TPAD;
    const float* ksb=ks+(h*16+e4*4)*TPAD;
    float acc[4][4];
    #pragma unroll
    for (int i=0;i<4;i++)
        #pragma unroll
        for (int j=0;j<4;j++) acc[i][j]=0.f;
    for (int pp=sub*64; pp<sub*64+64; pp++){
        float q0=qsb[pp],q1=qsb[TPAD+pp],q2=qsb[2*TPAD+pp],q3=qsb[3*TPAD+pp];
        float k0=ksb[pp],k1v=ksb[TPAD+pp],k2v=ksb[2*TPAD+pp],k3v=ksb[3*TPAD+pp];
        acc[0][0]=fmaf(q0,k0,acc[0][0]); acc[0][1]=fmaf(q0,k1v,acc[0][1]); acc[0][2]=fmaf(q0,k2v,acc[0][2]); acc[0][3]=fmaf(q0,k3v,acc[0][3]);
        acc[1][0]=fmaf(q1,k0,acc[1][0]); acc[1][1]=fmaf(q1,k1v,acc[1][1]); acc[1][2]=fmaf(q1,k2v,acc[1][2]); acc[1][3]=fmaf(q1,k3v,acc[1][3]);
        acc[2][0]=fmaf(q2,k0,acc[2][0]); acc[2][1]=fmaf(q2,k1v,acc[2][1]); acc[2][2]=fmaf(q2,k2v,acc[2][2]); acc[2][3]=fmaf(q2,k3v,acc[2][3]);
        acc[3][0]=fmaf(q3,k0,acc[3][0]); acc[3][1]=fmaf(q3,k1v,acc[3][1]); acc[3][2]=fmaf(q3,k2v,acc[3][2]); acc[3][3]=fmaf(q3,k3v,acc[3][3]);
    }
    #pragma unroll
    for (int i=0;i<4;i++)
        #pragma unroll
        for (int j=0;j<4;j++)
            red[sub*1024 + (h*16+d4*4+i)*16 + (e4*4+j)] = acc[i][j];
    if (t < 64){
        const float* qr=qs+t*TPAD;
        float a0=0,a1=0,a2=0,a3=0;
        for (int pp=0;pp<256;pp+=4){
            a0=fmaf(qr[pp+0],qr[pp+0],a0); a1=fmaf(qr[pp+1],qr[pp+1],a1);
            a2=fmaf(qr[pp+2],qr[pp+2],a2); a3=fmaf(qr[pp+3],qr[pp+3],a3);
        }
        g_sqp[(b*64+chunk)*64+t]=(a0+a1)+(a2+a3);
    } else if (t < 128){
        int ch=t-64;
        const float* kr=ks+ch*TPAD;
        float a0=0,a1=0,a2=0,a3=0;
        for (int pp=0;pp<256;pp+=4){
            a0=fmaf(kr[pp+0],kr[pp+0],a0); a1=fmaf(kr[pp+1],kr[pp+1],a1);
            a2=fmaf(kr[pp+2],kr[pp+2],a2); a3=fmaf(kr[pp+3],kr[pp+3],a3);
        }
        g_skp[(b*64+chunk)*64+ch]=(a0+a1)+(a2+a3);
    }
    __syncthreads();
    float* gout = g_Gpart + (b*64+chunk)*1024;
    for (int idx=t; idx<1024; idx+=256)
        gout[idx] = (red[idx]+red[1024+idx]) + (red[2048+idx]+red[3072+idx]);
}

// ------------ k4: reduce + normalize + softmax -> A --------------------------
__global__ void k4(const float* __restrict__ rescale)
{
    __shared__ float sG[1024];
    __shared__ float snq[64], snk[64];
    int b=blockIdx.x, t=threadIdx.x;
    for (int idx=t; idx<1024; idx+=256){
        float a=0.f;
        for (int c=0;c<64;c++) a += g_Gpart[(b*64+c)*1024+idx];
        sG[idx]=a;
    }
    if (t<64){
        float aq=0.f, ak=0.f;
        for (int c=0;c<64;c++){ aq+=g_sqp[(b*64+c)*64+t]; ak+=g_skp[(b*64+c)*64+t]; }
        snq[t]=sqrtf(aq)+1e-8f; snk[t]=sqrtf(ak)+1e-8f;
    }
    __syncthreads();
    if (t<64){
        int h=t>>4;
        float r=rescale[h], nq=snq[t];
        float ev[16]; float mx=-1e30f;
        #pragma unroll
        for (int e=0;e<16;e++){ ev[e]=sG[t*16+e]/(nq*snk[h*16+e])*r; mx=fmaxf(mx,ev[e]); }
        float ss=0.f;
        #pragma unroll
        for (int e=0;e<16;e++){ ev[e]=expf(ev[e]-mx); ss+=ev[e]; }
        float inv=1.f/ss;
        #pragma unroll
        for (int e=0;e<16;e++) g_A[b*1024 + t*16+e]=ev[e]*inv;
    }
}

// ------------ k4b: Weff[b] = blockdiag(A)^T folded into wo -------------------
__global__ void k4b(const float* __restrict__ wo)
{
    __shared__ float sA[1024];
    __shared__ float swo[4096];
    int b=blockIdx.x, t=threadIdx.x;
    for (int i=t;i<1024;i+=256) sA[i]=g_A[b*1024+i];
    for (int i=t;i<4096;i+=256) swo[i]=wo[i];
    __syncthreads();
    for (int idx=t; idx<4096; idx+=256){
        int cp=idx>>6, e=idx&63, h=e>>4, e15=e&15;
        float acc=0.f;
        #pragma unroll
        for (int d=0;d<16;d++)
            acc = fmaf(sA[h*256 + d*16 + e15], swo[(h*16+d)*64 + cp], acc);
        g_weffT[b*4096 + cp*64 + e] = acc;
    }
}

// ------------ k5: out = v @ WeffT + bo + xm ----------------------------------
__global__ void __launch_bounds__(256,2)
k5(const float* __restrict__ bo, float* __restrict__ out)
{
    __shared__ __align__(16) float sw[4096];
    __shared__ float sbo[64];
    int t=threadIdx.x;
    int gp=blockIdx.x*256+t;
    int b=gp>>14, p=gp&(NPIX-1);
    for (int i=t;i<4096;i+=256) sw[i]=g_weffT[b*4096+i];
    if (t<64) sbo[t]=bo[t];
    u64 vp[32];
    #pragma unroll
    for (int e=0;e<64;e+=2) vp[e>>1]=pack2(g_v[e*BN+gp], g_v[(e+1)*BN+gp]);
    __syncthreads();
    #pragma unroll 2
    for (int cp=0;cp<64;cp++){
        float d = dot64p(sw+cp*64, vp) + sbo[cp] + g_xm[cp*BN+gp];
        out[(size_t)(b*64+cp)*NPIX + p] = d;
    }
}

// ------------ launch ----------------------------------------------------------
extern "C" void kernel_launch(void* const* d_in, const int* in_sizes, int n_in,
                              void* d_out, int out_size)
{
    const float* x   =(const float*)d_in[0];
    const float* sem =(const float*)d_in[1];
    const float* wa  =(const float*)d_in[2];
    const float* ba  =(const float*)d_in[3];
    const float* wb  =(const float*)d_in[4];
    const float* bb  =(const float*)d_in[5];
    const float* inw =(const float*)d_in[6];
    const float* inb =(const float*)d_in[7];
    const float* w1  =(const float*)d_in[8];
    const float* b1  =(const float*)d_in[9];
    const float* gm1 =(const float*)d_in[10];
    const float* be1 =(const float*)d_in[11];
    const float* w2  =(const float*)d_in[12];
    const float* b2  =(const float*)d_in[13];
    const float* gm2 =(const float*)d_in[14];
    const float* be2 =(const float*)d_in[15];
    const float* w3  =(const float*)d_in[16];
    const float* b3  =(const float*)d_in[17];
    const float* wq  =(const float*)d_in[18];
    const float* bq  =(const float*)d_in[19];
    const float* wk  =(const float*)d_in[20];
    const float* bk  =(const float*)d_in[21];
    const float* wv  =(const float*)d_in[22];
    const float* bv  =(const float*)d_in[23];
    const float* wo  =(const float*)d_in[24];
    const float* bo  =(const float*)d_in[25];
    const float* rescale=(const float*)d_in[26];
    float* out=(float*)d_out;

    cudaFuncSetAttribute(k1, cudaFuncAttributeMaxDynamicSharedMemorySize, 22016*4);
    cudaFuncSetAttribute(k2, cudaFuncAttributeMaxDynamicSharedMemorySize, 50048*4);
    cudaFuncSetAttribute(k3, cudaFuncAttributeMaxDynamicSharedMemorySize, 36992*4);

    kprep<<<64,256>>>(wa,ba,wb,bb,inw,wk,wv,wq,w1,w2);
    k1<<<256,256,22016*4>>>(x,sem,inb,bk,bv);
    k2<<<256,256,50048*4>>>(x,b1,gm1,be1,b2,gm2,be2,w3,b3,bq);
    k3<<<dim3(64,4),256,36992*4>>>();
    k4<<<4,256>>>(rescale);
    k4b<<<4,256>>>(wo);
    k5<<<256,256>>>(bo,out);
}